// round 9
// baseline (speedup 1.0000x reference)
#include <cuda_runtime.h>
#include <cuda_bf16.h>
#include <cstdint>

#define NPTS 262144
#define DIMS 128
#define KCL  1024
#define TM   128
#define TN   128
#define NTILES (KCL / TN)   // 8
#define NTHR 512

// ---- smem map (dynamic, from 1KB-aligned base) ----
#define SM_XHI 0
#define SM_XLO 32768
#define SM_C   65536            // 2 buffers x (hi 32K + lo 32K)
#define SM_CSQ (65536 + 131072) // 4KB
#define SM_XSQ (SM_CSQ + 4096)  // 512B
#define SM_BYTES (SM_XSQ + 512 + 1024)

__device__ float g_csq[KCL];
__device__ __align__(16) unsigned char g_chi[KCL * DIMS * 2];  // bf16, row-major [k][d]
__device__ __align__(16) unsigned char g_clo[KCL * DIMS * 2];

// ---------------- PTX helpers (sm_80+ baseline ISA only) ----------------
__device__ __forceinline__ uint32_t smem_u32(const void* p) {
    uint32_t a;
    asm("{ .reg .u64 t; cvta.to.shared.u64 t, %1; cvt.u32.u64 %0, t; }" : "=r"(a) : "l"(p));
    return a;
}
#define LDSM_X4(r0, r1, r2, r3, addr) \
    asm volatile("ldmatrix.sync.aligned.m8n8.x4.shared.b16 {%0,%1,%2,%3}, [%4];" \
                 : "=r"(r0), "=r"(r1), "=r"(r2), "=r"(r3) : "r"(addr))
#define MMA_BF16(d, a, b) \
    asm volatile("mma.sync.aligned.m16n8k16.row.col.f32.bf16.bf16.f32 " \
                 "{%0,%1,%2,%3}, {%4,%5,%6,%7}, {%8,%9}, {%0,%1,%2,%3};" \
                 : "+f"((d)[0]), "+f"((d)[1]), "+f"((d)[2]), "+f"((d)[3]) \
                 : "r"((a)[0]), "r"((a)[1]), "r"((a)[2]), "r"((a)[3]), \
                   "r"((b)[0]), "r"((b)[1]))
#define CP_ASYNC16(dst, src) \
    asm volatile("cp.async.cg.shared.global [%0], [%1], 16;" :: "r"(dst), "l"(src))
#define CP_COMMIT() asm volatile("cp.async.commit_group;" ::: "memory")
#define CP_WAIT(n)  asm volatile("cp.async.wait_group %0;" :: "n"(n) : "memory")

// ---------------- merged prep kernel (csq + bf16 split) ----------------
__global__ void prep_kernel(const float* __restrict__ C) {
    int idx = blockIdx.x * blockDim.x + threadIdx.x;   // over K*D
    if (idx < KCL * DIMS) {
        float v = C[idx];
        __nv_bfloat16 hi = __float2bfloat16(v);
        __nv_bfloat16 lo = __float2bfloat16(v - __bfloat162float(hi));
        *(__nv_bfloat16*)(g_chi + (size_t)idx * 2) = hi;
        *(__nv_bfloat16*)(g_clo + (size_t)idx * 2) = lo;
    }
    if (idx < KCL) {
        const float4* row = (const float4*)(C + (size_t)idx * DIMS);
        float s = 0.f;
#pragma unroll
        for (int i = 0; i < DIMS / 4; i++) {
            float4 v = row[i];
            s += v.x * v.x + v.y * v.y + v.z * v.z + v.w * v.w;
        }
        g_csq[idx] = s;
    }
}

// ---------------- main fused kernel ----------------
__global__ void __launch_bounds__(NTHR, 1)
kmeans_mma_kernel(const float* __restrict__ X, const float* __restrict__ Cf,
                  float* __restrict__ out)
{
    extern __shared__ unsigned char smraw[];
    uint32_t base = (smem_u32(smraw) + 1023u) & ~1023u;
    unsigned char* sm = smraw + (base - smem_u32(smraw));

    const int t    = threadIdx.x;
    const int lane = t & 31;
    const int wid  = t >> 5;
    const int wm   = wid & 3;    // warp row  (32 pts)
    const int wn   = wid >> 2;   // warp col  (32 clusters)
    const int pbase = blockIdx.x * TM;

    auto cp_tile = [&](int ct, int buf) {
        uint32_t dbase = base + SM_C + buf * 65536;
#pragma unroll
        for (int i = 0; i < 4; i++) {
            int idx = t + NTHR * i;
            int row = idx >> 4;
            int c   = idx & 15;
            uint32_t doff = (uint32_t)row * 256 + (uint32_t)((c ^ (row & 7)) << 4);
            size_t   soff = (size_t)ct * 32768 + (size_t)row * 256 + (size_t)c * 16;
            CP_ASYNC16(dbase + doff,         g_chi + soff);
            CP_ASYNC16(dbase + 32768 + doff, g_clo + soff);
        }
        CP_COMMIT();
    };
    cp_tile(0, 0);
    cp_tile(1, 1);

    float* csq_s = (float*)(sm + SM_CSQ);
    float* xsq_s = (float*)(sm + SM_XSQ);
#pragma unroll
    for (int k = 0; k < 2; k++) csq_s[t + NTHR * k] = g_csq[t + NTHR * k];

    // ---- build X hi/lo tiles in smem (swizzled 256B rows) ----
    {
        const float4* Xg = (const float4*)(X + (size_t)pbase * DIMS);
#pragma unroll
        for (int i = 0; i < 4; i++) {
            int idx = t + NTHR * i;
            int row = idx >> 4;
            int c   = idx & 15;
            float4 v0 = Xg[row * 32 + c * 2];
            float4 v1 = Xg[row * 32 + c * 2 + 1];
            float f[8] = {v0.x, v0.y, v0.z, v0.w, v1.x, v1.y, v1.z, v1.w};
            union { __nv_bfloat16 b[8]; uint4 u; } ph, pl;
#pragma unroll
            for (int e = 0; e < 8; e++) {
                __nv_bfloat16 h = __float2bfloat16(f[e]);
                ph.b[e] = h;
                pl.b[e] = __float2bfloat16(f[e] - __bfloat162float(h));
            }
            uint32_t doff = (uint32_t)row * 256 + (uint32_t)((c ^ (row & 7)) << 4);
            *(uint4*)(sm + SM_XHI + doff) = ph.u;
            *(uint4*)(sm + SM_XLO + doff) = pl.u;
        }
    }

    // ---- per-point ||x||^2 (makes scores positive -> raw-bits-sortable) ----
    if (t < TM) {
        const float4* xr = (const float4*)(X + (size_t)(pbase + t) * DIMS);
        float s = 0.f;
#pragma unroll 8
        for (int i = 0; i < DIMS / 4; i++) {
            float4 v = xr[i];
            s += v.x * v.x + v.y * v.y + v.z * v.z + v.w * v.w;
        }
        xsq_s[t] = s;
    }
    __syncthreads();

    const int arow0 = wm * 32 + (lane & 15);
    const uint32_t akb = (uint32_t)(lane >> 4) * 16;
    const int brow0 = wn * 32 + (lane & 7) + ((lane >> 4) << 3);
    const uint32_t bkb = (uint32_t)((lane >> 3) & 1) * 16;
    const int r  = lane >> 2;
    const int c2 = (lane & 3) * 2;

    // per-slot ||x||^2 (slot j = mi*2 + (q>>1))
    float xq[4];
#pragma unroll
    for (int mi = 0; mi < 2; mi++)
#pragma unroll
        for (int h = 0; h < 2; h++)
            xq[mi * 2 + h] = xsq_s[wm * 32 + mi * 16 + h * 8 + r];

    // branchless top-2: keys (positive-float-bits << 32) | cluster_idx
    uint64_t k1[4], k2[4];
#pragma unroll
    for (int j = 0; j < 4; j++) { k1[j] = ~0ull; k2[j] = ~0ull; }

    for (int ct = 0; ct < NTILES; ct++) {
        if (ct < NTILES - 1) { CP_WAIT(1); } else { CP_WAIT(0); }
        __syncthreads();

        const uint32_t chb = base + SM_C + (ct & 1) * 65536;
        const uint32_t clb = chb + 32768;

        float acc[2][4][4];
#pragma unroll
        for (int mi = 0; mi < 2; mi++)
#pragma unroll
            for (int ni = 0; ni < 4; ni++)
#pragma unroll
                for (int q = 0; q < 4; q++) acc[mi][ni][q] = 0.f;

#pragma unroll
        for (int ks = 0; ks < 8; ks++) {
            uint32_t ahi[2][4], alo[2][4], bhi[4][2], blo[4][2];
#pragma unroll
            for (int mi = 0; mi < 2; mi++) {
                int row = arow0 + mi * 16;
                uint32_t off = (uint32_t)row * 256 +
                               (((uint32_t)ks * 32 + akb) ^ (uint32_t)((row & 7) << 4));
                LDSM_X4(ahi[mi][0], ahi[mi][1], ahi[mi][2], ahi[mi][3], base + SM_XHI + off);
                LDSM_X4(alo[mi][0], alo[mi][1], alo[mi][2], alo[mi][3], base + SM_XLO + off);
            }
#pragma unroll
            for (int nh = 0; nh < 2; nh++) {
                int row = brow0 + nh * 16;
                uint32_t off = (uint32_t)row * 256 +
                               (((uint32_t)ks * 32 + bkb) ^ (uint32_t)((row & 7) << 4));
                LDSM_X4(bhi[2 * nh][0], bhi[2 * nh][1], bhi[2 * nh + 1][0], bhi[2 * nh + 1][1],
                        chb + off);
                LDSM_X4(blo[2 * nh][0], blo[2 * nh][1], blo[2 * nh + 1][0], blo[2 * nh + 1][1],
                        clb + off);
            }
#pragma unroll
            for (int mi = 0; mi < 2; mi++)
#pragma unroll
                for (int ni = 0; ni < 4; ni++) {
                    MMA_BF16(acc[mi][ni], ahi[mi], bhi[ni]);
                    MMA_BF16(acc[mi][ni], ahi[mi], blo[ni]);
                    MMA_BF16(acc[mi][ni], alo[mi], bhi[ni]);
                }
        }

        // ---- tile epilogue: dis = xsq + csq - 2*cross (>=0), branchless top-2 ----
#pragma unroll
        for (int mi = 0; mi < 2; mi++)
#pragma unroll
            for (int ni = 0; ni < 4; ni++) {
                int cb = ct * TN + wn * 32 + ni * 8 + c2;
#pragma unroll
                for (int q = 0; q < 4; q++) {
                    int j = mi * 2 + (q >> 1);
                    uint32_t cidx = (uint32_t)(cb + (q & 1));
                    float dis = fmaf(acc[mi][ni][q], -2.f, csq_s[cidx]) + xq[j];
                    uint64_t k = ((uint64_t)__float_as_uint(dis) << 32) | cidx;
                    bool p = k < k1[j];
                    uint64_t m = p ? k1[j] : k;
                    k1[j] = p ? k : k1[j];
                    k2[j] = (m < k2[j]) ? m : k2[j];
                }
            }

        __syncthreads();
        if (ct + 2 < NTILES) cp_tile(ct + 2, ct & 1);
    }

    // ---- cross-lane/warp top-2 reduction (reuse C buffer smem) ----
    uint64_t* rd = (uint64_t*)(sm + SM_C);   // [128 rows][16 slots][2]
    int slot = wn * 4 + (lane & 3);
#pragma unroll
    for (int mi = 0; mi < 2; mi++)
#pragma unroll
        for (int h = 0; h < 2; h++) {
            int j = mi * 2 + h;
            int row = wm * 32 + mi * 16 + h * 8 + r;
            rd[row * 32 + slot * 2 + 0] = k1[j];
            rd[row * 32 + slot * 2 + 1] = k2[j];
        }
    __syncthreads();

    if (t < TM) {
        uint64_t g1 = ~0ull, g2 = ~0ull;
#pragma unroll
        for (int s = 0; s < 32; s++) {
            uint64_t k = rd[t * 32 + s];
            bool p = k < g1;
            uint64_t m = p ? g1 : k;
            g1 = p ? k : g1;
            g2 = (m < g2) ? m : g2;
        }
        int j1 = (int)(uint32_t)g1;
        int j2 = (int)(uint32_t)g2;

        // ---- exact fp32 re-check of the two candidates ----
        const float4* xr = (const float4*)(X + (size_t)(pbase + t) * DIMS);
        const float4* p1 = (const float4*)(Cf + (size_t)j1 * DIMS);
        const float4* p2 = (const float4*)(Cf + (size_t)j2 * DIMS);
        float a1 = 0.f, a2 = 0.f, a3 = 0.f, a4 = 0.f;
        float e1 = 0.f, e2 = 0.f, e3 = 0.f, e4 = 0.f;
#pragma unroll 8
        for (int i = 0; i < DIMS / 4; i++) {
            float4 xv = xr[i], u = p1[i], w = p2[i];
            a1 += xv.x * u.x; a2 += xv.y * u.y; a3 += xv.z * u.z; a4 += xv.w * u.w;
            e1 += xv.x * w.x; e2 += xv.y * w.y; e3 += xv.z * w.z; e4 += xv.w * w.w;
        }
        float cr1 = (a1 + a2) + (a3 + a4);
        float cr2 = (e1 + e2) + (e3 + e4);
        float s1 = fmaf(cr1, -2.f, csq_s[j1]);
        float s2 = fmaf(cr2, -2.f, csq_s[j2]);
        int lab = (s2 < s1 || (s2 == s1 && j2 < j1)) ? j2 : j1;
        out[pbase + t] = (float)lab;   // __output__ is float32
    }
}

extern "C" void kernel_launch(void* const* d_in, const int* in_sizes, int n_in,
                              void* d_out, int out_size) {
    const float* X = (const float*)d_in[0];
    const float* C = (const float*)d_in[1];
    if (n_in >= 2 && in_sizes[0] < in_sizes[1]) {
        X = (const float*)d_in[1];
        C = (const float*)d_in[0];
    }
    float* out = (float*)d_out;

    cudaFuncSetAttribute(kmeans_mma_kernel,
                         cudaFuncAttributeMaxDynamicSharedMemorySize, SM_BYTES);

    prep_kernel<<<KCL * DIMS / 256, 256>>>(C);
    kmeans_mma_kernel<<<NPTS / TM, NTHR, SM_BYTES>>>(X, C, out);
}

// round 10
// speedup vs baseline: 1.1142x; 1.1142x over previous
#include <cuda_runtime.h>
#include <cuda_bf16.h>
#include <cstdint>

#define NPTS 262144
#define DIMS 128
#define KCL  1024
#define TM   128
#define TN   128
#define NTILES (KCL / TN)   // 8
#define NTHR 512

// ---- smem map (dynamic, from 1KB-aligned base) ----
#define SM_XHI 0
#define SM_C   32768                 // 2 buffers x (hi 32K + lo 32K)
#define SM_CSQ (32768 + 131072)      // 4KB
#define SM_XSQ (SM_CSQ + 4096)       // 512B
#define SM_BYTES (SM_XSQ + 512 + 1024)

__device__ float g_csq[KCL];
__device__ __align__(16) unsigned char g_chi[KCL * DIMS * 2];  // bf16, row-major
__device__ __align__(16) unsigned char g_clo[KCL * DIMS * 2];

// ---------------- PTX helpers (sm_80+ baseline ISA only) ----------------
__device__ __forceinline__ uint32_t smem_u32(const void* p) {
    uint32_t a;
    asm("{ .reg .u64 t; cvta.to.shared.u64 t, %1; cvt.u32.u64 %0, t; }" : "=r"(a) : "l"(p));
    return a;
}
#define LDSM_X4(r0, r1, r2, r3, addr) \
    asm volatile("ldmatrix.sync.aligned.m8n8.x4.shared.b16 {%0,%1,%2,%3}, [%4];" \
                 : "=r"(r0), "=r"(r1), "=r"(r2), "=r"(r3) : "r"(addr))
#define MMA_BF16(d, a, b) \
    asm volatile("mma.sync.aligned.m16n8k16.row.col.f32.bf16.bf16.f32 " \
                 "{%0,%1,%2,%3}, {%4,%5,%6,%7}, {%8,%9}, {%0,%1,%2,%3};" \
                 : "+f"((d)[0]), "+f"((d)[1]), "+f"((d)[2]), "+f"((d)[3]) \
                 : "r"((a)[0]), "r"((a)[1]), "r"((a)[2]), "r"((a)[3]), \
                   "r"((b)[0]), "r"((b)[1]))
#define CP_ASYNC16(dst, src) \
    asm volatile("cp.async.cg.shared.global [%0], [%1], 16;" :: "r"(dst), "l"(src))
#define CP_COMMIT() asm volatile("cp.async.commit_group;" ::: "memory")
#define CP_WAIT(n)  asm volatile("cp.async.wait_group %0;" :: "n"(n) : "memory")

// ---------------- merged prep kernel (csq + bf16 split of C) ----------------
__global__ void prep_kernel(const float* __restrict__ C) {
    int idx = blockIdx.x * blockDim.x + threadIdx.x;   // over K*D
    if (idx < KCL * DIMS) {
        float v = C[idx];
        __nv_bfloat16 hi = __float2bfloat16(v);
        __nv_bfloat16 lo = __float2bfloat16(v - __bfloat162float(hi));
        *(__nv_bfloat16*)(g_chi + (size_t)idx * 2) = hi;
        *(__nv_bfloat16*)(g_clo + (size_t)idx * 2) = lo;
    }
    if (idx < KCL) {
        const float4* row = (const float4*)(C + (size_t)idx * DIMS);
        float s = 0.f;
#pragma unroll
        for (int i = 0; i < DIMS / 4; i++) {
            float4 v = row[i];
            s += v.x * v.x + v.y * v.y + v.z * v.z + v.w * v.w;
        }
        g_csq[idx] = s;
    }
}

// ---------------- main fused kernel ----------------
__global__ void __launch_bounds__(NTHR, 1)
kmeans_mma_kernel(const float* __restrict__ X, const float* __restrict__ Cf,
                  float* __restrict__ out)
{
    extern __shared__ unsigned char smraw[];
    uint32_t base = (smem_u32(smraw) + 1023u) & ~1023u;
    unsigned char* sm = smraw + (base - smem_u32(smraw));

    const int t    = threadIdx.x;
    const int lane = t & 31;
    const int wid  = t >> 5;
    const int wm   = wid & 3;    // warp row  (32 pts)
    const int wn   = wid >> 2;   // warp col  (32 clusters)
    const int pbase = blockIdx.x * TM;

    auto cp_tile = [&](int ct, int buf) {
        uint32_t dbase = base + SM_C + buf * 65536;
#pragma unroll
        for (int i = 0; i < 4; i++) {
            int idx = t + NTHR * i;
            int row = idx >> 4;
            int c   = idx & 15;
            uint32_t doff = (uint32_t)row * 256 + (uint32_t)((c ^ (row & 7)) << 4);
            size_t   soff = (size_t)ct * 32768 + (size_t)row * 256 + (size_t)c * 16;
            CP_ASYNC16(dbase + doff,         g_chi + soff);
            CP_ASYNC16(dbase + 32768 + doff, g_clo + soff);
        }
        CP_COMMIT();
    };
    cp_tile(0, 0);
    cp_tile(1, 1);

    float* csq_s = (float*)(sm + SM_CSQ);
    float* xsq_s = (float*)(sm + SM_XSQ);
#pragma unroll
    for (int k = 0; k < 2; k++) csq_s[t + NTHR * k] = g_csq[t + NTHR * k];

    // ---- build X hi tile in smem (swizzled 256B rows); no lo needed ----
    {
        const float4* Xg = (const float4*)(X + (size_t)pbase * DIMS);
#pragma unroll
        for (int i = 0; i < 4; i++) {
            int idx = t + NTHR * i;
            int row = idx >> 4;
            int c   = idx & 15;
            float4 v0 = Xg[row * 32 + c * 2];
            float4 v1 = Xg[row * 32 + c * 2 + 1];
            float f[8] = {v0.x, v0.y, v0.z, v0.w, v1.x, v1.y, v1.z, v1.w};
            union { __nv_bfloat16 b[8]; uint4 u; } ph;
#pragma unroll
            for (int e = 0; e < 8; e++) ph.b[e] = __float2bfloat16(f[e]);
            uint32_t doff = (uint32_t)row * 256 + (uint32_t)((c ^ (row & 7)) << 4);
            *(uint4*)(sm + SM_XHI + doff) = ph.u;
        }
    }

    // ---- per-point ||x||^2 (scores positive -> raw-bits-sortable) ----
    if (t < TM) {
        const float4* xr = (const float4*)(X + (size_t)(pbase + t) * DIMS);
        float s = 0.f;
#pragma unroll 8
        for (int i = 0; i < DIMS / 4; i++) {
            float4 v = xr[i];
            s += v.x * v.x + v.y * v.y + v.z * v.z + v.w * v.w;
        }
        xsq_s[t] = s;
    }
    __syncthreads();

    const int arow0 = wm * 32 + (lane & 15);
    const uint32_t akb = (uint32_t)(lane >> 4) * 16;
    const int brow0 = wn * 32 + (lane & 7) + ((lane >> 4) << 3);
    const uint32_t bkb = (uint32_t)((lane >> 3) & 1) * 16;
    const int r  = lane >> 2;

    float xq[4];
#pragma unroll
    for (int mi = 0; mi < 2; mi++)
#pragma unroll
        for (int h = 0; h < 2; h++)
            xq[mi * 2 + h] = xsq_s[wm * 32 + mi * 16 + h * 8 + r];

    // per-slot top-3, u32 keys: (dist_bits & ~63) | local6
    uint32_t k1[4], k2[4], k3[4];
#pragma unroll
    for (int j = 0; j < 4; j++) { k1[j] = ~0u; k2[j] = ~0u; k3[j] = ~0u; }

    for (int ct = 0; ct < NTILES; ct++) {
        if (ct < NTILES - 1) { CP_WAIT(1); } else { CP_WAIT(0); }
        __syncthreads();

        const uint32_t chb = base + SM_C + (ct & 1) * 65536;
        const uint32_t clb = chb + 32768;

        float acc[2][4][4];
#pragma unroll
        for (int mi = 0; mi < 2; mi++)
#pragma unroll
            for (int ni = 0; ni < 4; ni++)
#pragma unroll
                for (int q = 0; q < 4; q++) acc[mi][ni][q] = 0.f;

#pragma unroll
        for (int ks = 0; ks < 8; ks++) {
            uint32_t ahi[2][4], bhi[4][2], blo[4][2];
#pragma unroll
            for (int mi = 0; mi < 2; mi++) {
                int row = arow0 + mi * 16;
                uint32_t off = (uint32_t)row * 256 +
                               (((uint32_t)ks * 32 + akb) ^ (uint32_t)((row & 7) << 4));
                LDSM_X4(ahi[mi][0], ahi[mi][1], ahi[mi][2], ahi[mi][3], base + SM_XHI + off);
            }
#pragma unroll
            for (int nh = 0; nh < 2; nh++) {
                int row = brow0 + nh * 16;
                uint32_t off = (uint32_t)row * 256 +
                               (((uint32_t)ks * 32 + bkb) ^ (uint32_t)((row & 7) << 4));
                LDSM_X4(bhi[2 * nh][0], bhi[2 * nh][1], bhi[2 * nh + 1][0], bhi[2 * nh + 1][1],
                        chb + off);
                LDSM_X4(blo[2 * nh][0], blo[2 * nh][1], blo[2 * nh + 1][0], blo[2 * nh + 1][1],
                        clb + off);
            }
#pragma unroll
            for (int mi = 0; mi < 2; mi++)
#pragma unroll
                for (int ni = 0; ni < 4; ni++) {
                    MMA_BF16(acc[mi][ni], ahi[mi], bhi[ni]);
                    MMA_BF16(acc[mi][ni], ahi[mi], blo[ni]);
                }
        }

        // ---- tile epilogue: dis = xsq + csq - 2*cross, branchless top-3 (u32) ----
#pragma unroll
        for (int mi = 0; mi < 2; mi++)
#pragma unroll
            for (int ni = 0; ni < 4; ni++) {
                int cb = ct * TN + wn * 32 + ni * 8 + (lane & 3) * 2;
#pragma unroll
                for (int q = 0; q < 4; q++) {
                    int j = mi * 2 + (q >> 1);
                    int q1 = q & 1;
                    float dis = fmaf(acc[mi][ni][q], -2.f, csq_s[cb + q1]) + xq[j];
                    uint32_t local6 = (uint32_t)((ct << 3) | (ni << 1) | q1);
                    uint32_t key = (__float_as_uint(dis) & ~63u) | local6;
                    uint32_t m1 = min(k1[j], key), M1 = max(k1[j], key);
                    k1[j] = m1;
                    uint32_t m2 = min(k2[j], M1),  M2 = max(k2[j], M1);
                    k2[j] = m2;
                    k3[j] = min(k3[j], M2);
                }
            }

        __syncthreads();
        if (ct + 2 < NTILES) cp_tile(ct + 2, ct & 1);
    }

    // ---- cross-thread candidate dump (reuse C buffer smem) ----
    uint32_t* rd = (uint32_t*)(sm + SM_C);   // [128 pts][16 slots][3 keys]
    int slot = wn * 4 + (lane & 3);
#pragma unroll
    for (int mi = 0; mi < 2; mi++)
#pragma unroll
        for (int h = 0; h < 2; h++) {
            int j = mi * 2 + h;
            int row = wm * 32 + mi * 16 + h * 8 + r;
            rd[row * 48 + slot * 3 + 0] = k1[j];
            rd[row * 48 + slot * 3 + 1] = k2[j];
            rd[row * 48 + slot * 3 + 2] = k3[j];
        }
    __syncthreads();

    if (t < TM) {
        // global top-4 (branchless insert, keys + decoded cluster ids)
        uint32_t tk[4] = {~0u, ~0u, ~0u, ~0u};
        int      ti[4] = {0, 0, 0, 0};
#pragma unroll
        for (int s = 0; s < 16; s++) {
#pragma unroll
            for (int e = 0; e < 3; e++) {
                uint32_t key = rd[t * 48 + s * 3 + e];
                uint32_t local = key & 63u;
                int cid = (int)(((local >> 3) << 7) | ((uint32_t)(s >> 2) << 5) |
                                (((local >> 1) & 3u) << 3) | ((uint32_t)(s & 3) << 1) |
                                (local & 1u));
#pragma unroll
                for (int u = 0; u < 4; u++) {
                    bool p = key < tk[u];
                    uint32_t km = p ? key : tk[u];  uint32_t kM = p ? tk[u] : key;
                    int im = p ? cid : ti[u];       int iM = p ? ti[u] : cid;
                    tk[u] = km; ti[u] = im; key = kM; cid = iM;
                }
            }
        }

        // ---- exact fp32 recheck of the 4 candidates ----
        const float4* xr = (const float4*)(X + (size_t)(pbase + t) * DIMS);
        float bestd = 3.4e38f;
        int   bestc = KCL;
#pragma unroll
        for (int u = 0; u < 4; u++) {
            int c = ti[u];
            const float4* pr = (const float4*)(Cf + (size_t)c * DIMS);
            float a1 = 0.f, a2 = 0.f, a3 = 0.f, a4 = 0.f;
#pragma unroll 8
            for (int i = 0; i < DIMS / 4; i++) {
                float4 xv = xr[i], cv = pr[i];
                a1 += xv.x * cv.x; a2 += xv.y * cv.y;
                a3 += xv.z * cv.z; a4 += xv.w * cv.w;
            }
            float cr = (a1 + a2) + (a3 + a4);
            float d  = fmaf(cr, -2.f, csq_s[c]);
            if (d < bestd || (d == bestd && c < bestc)) { bestd = d; bestc = c; }
        }
        out[pbase + t] = (float)bestc;   // __output__ is float32
    }
}

extern "C" void kernel_launch(void* const* d_in, const int* in_sizes, int n_in,
                              void* d_out, int out_size) {
    const float* X = (const float*)d_in[0];
    const float* C = (const float*)d_in[1];
    if (n_in >= 2 && in_sizes[0] < in_sizes[1]) {
        X = (const float*)d_in[1];
        C = (const float*)d_in[0];
    }
    float* out = (float*)d_out;

    cudaFuncSetAttribute(kmeans_mma_kernel,
                         cudaFuncAttributeMaxDynamicSharedMemorySize, SM_BYTES);

    prep_kernel<<<KCL * DIMS / 256, 256>>>(C);
    kmeans_mma_kernel<<<NPTS / TM, NTHR, SM_BYTES>>>(X, C, out);
}

// round 11
// speedup vs baseline: 1.1156x; 1.0013x over previous
#include <cuda_runtime.h>
#include <cuda_bf16.h>
#include <cstdint>

#define NPTS 262144
#define DIMS 128
#define KCL  1024
#define TM   128
#define TN   128
#define NTILES (KCL / TN)   // 8
#define NTHR 512

// ---- smem map (dynamic, from 1KB-aligned base) ----
#define SM_XHI 0
#define SM_C   32768                 // 2 buffers x (hi 32K + lo 32K)
#define SM_CSQ (32768 + 131072)      // 4KB
#define SM_XSQ (SM_CSQ + 4096)       // 512B
#define SM_BYTES (SM_XSQ + 512 + 1024)

__device__ float g_csq[KCL];
__device__ __align__(16) unsigned char g_chi[KCL * DIMS * 2];  // bf16, row-major
__device__ __align__(16) unsigned char g_clo[KCL * DIMS * 2];

// ---------------- PTX helpers (sm_80+ baseline ISA only) ----------------
__device__ __forceinline__ uint32_t smem_u32(const void* p) {
    uint32_t a;
    asm("{ .reg .u64 t; cvta.to.shared.u64 t, %1; cvt.u32.u64 %0, t; }" : "=r"(a) : "l"(p));
    return a;
}
#define LDSM_X4(r0, r1, r2, r3, addr) \
    asm volatile("ldmatrix.sync.aligned.m8n8.x4.shared.b16 {%0,%1,%2,%3}, [%4];" \
                 : "=r"(r0), "=r"(r1), "=r"(r2), "=r"(r3) : "r"(addr))
#define MMA_BF16(d, a, b) \
    asm volatile("mma.sync.aligned.m16n8k16.row.col.f32.bf16.bf16.f32 " \
                 "{%0,%1,%2,%3}, {%4,%5,%6,%7}, {%8,%9}, {%0,%1,%2,%3};" \
                 : "+f"((d)[0]), "+f"((d)[1]), "+f"((d)[2]), "+f"((d)[3]) \
                 : "r"((a)[0]), "r"((a)[1]), "r"((a)[2]), "r"((a)[3]), \
                   "r"((b)[0]), "r"((b)[1]))
#define CP_ASYNC16(dst, src) \
    asm volatile("cp.async.cg.shared.global [%0], [%1], 16;" :: "r"(dst), "l"(src))
#define CP_COMMIT() asm volatile("cp.async.commit_group;" ::: "memory")
#define CP_WAIT(n)  asm volatile("cp.async.wait_group %0;" :: "n"(n) : "memory")

// ---------------- merged prep kernel (csq + bf16 split of C) ----------------
__global__ void prep_kernel(const float* __restrict__ C) {
    int idx = blockIdx.x * blockDim.x + threadIdx.x;   // over K*D
    if (idx < KCL * DIMS) {
        float v = C[idx];
        __nv_bfloat16 hi = __float2bfloat16(v);
        __nv_bfloat16 lo = __float2bfloat16(v - __bfloat162float(hi));
        *(__nv_bfloat16*)(g_chi + (size_t)idx * 2) = hi;
        *(__nv_bfloat16*)(g_clo + (size_t)idx * 2) = lo;
    }
    if (idx < KCL) {
        const float4* row = (const float4*)(C + (size_t)idx * DIMS);
        float s = 0.f;
#pragma unroll
        for (int i = 0; i < DIMS / 4; i++) {
            float4 v = row[i];
            s += v.x * v.x + v.y * v.y + v.z * v.z + v.w * v.w;
        }
        g_csq[idx] = s;
    }
}

// ---------------- main fused kernel ----------------
__global__ void __launch_bounds__(NTHR, 1)
kmeans_mma_kernel(const float* __restrict__ X, const float* __restrict__ Cf,
                  float* __restrict__ out)
{
    extern __shared__ unsigned char smraw[];
    uint32_t base = (smem_u32(smraw) + 1023u) & ~1023u;
    unsigned char* sm = smraw + (base - smem_u32(smraw));

    const int t    = threadIdx.x;
    const int lane = t & 31;
    const int wid  = t >> 5;
    const int wm   = wid & 3;    // warp row  (32 pts)
    const int wn   = wid >> 2;   // warp col  (32 clusters)
    const int pbase = blockIdx.x * TM;

    auto cp_tile = [&](int ct, int buf) {
        uint32_t dbase = base + SM_C + buf * 65536;
#pragma unroll
        for (int i = 0; i < 4; i++) {
            int idx = t + NTHR * i;
            int row = idx >> 4;
            int c   = idx & 15;
            uint32_t doff = (uint32_t)row * 256 + (uint32_t)((c ^ (row & 7)) << 4);
            size_t   soff = (size_t)ct * 32768 + (size_t)row * 256 + (size_t)c * 16;
            CP_ASYNC16(dbase + doff,         g_chi + soff);
            CP_ASYNC16(dbase + 32768 + doff, g_clo + soff);
        }
        CP_COMMIT();
    };
    cp_tile(0, 0);
    cp_tile(1, 1);

    float* csq_s = (float*)(sm + SM_CSQ);
    float* xsq_s = (float*)(sm + SM_XSQ);
#pragma unroll
    for (int k = 0; k < 2; k++) csq_s[t + NTHR * k] = g_csq[t + NTHR * k];

    // ---- build X hi tile in smem (swizzled 256B rows) ----
    {
        const float4* Xg = (const float4*)(X + (size_t)pbase * DIMS);
#pragma unroll
        for (int i = 0; i < 4; i++) {
            int idx = t + NTHR * i;
            int row = idx >> 4;
            int c   = idx & 15;
            float4 v0 = Xg[row * 32 + c * 2];
            float4 v1 = Xg[row * 32 + c * 2 + 1];
            float f[8] = {v0.x, v0.y, v0.z, v0.w, v1.x, v1.y, v1.z, v1.w};
            union { __nv_bfloat16 b[8]; uint4 u; } ph;
#pragma unroll
            for (int e = 0; e < 8; e++) ph.b[e] = __float2bfloat16(f[e]);
            uint32_t doff = (uint32_t)row * 256 + (uint32_t)((c ^ (row & 7)) << 4);
            *(uint4*)(sm + SM_XHI + doff) = ph.u;
        }
    }

    // ---- per-point ||x||^2 (scores positive -> raw-bits-sortable) ----
    if (t < TM) {
        const float4* xr = (const float4*)(X + (size_t)(pbase + t) * DIMS);
        float s = 0.f;
#pragma unroll 8
        for (int i = 0; i < DIMS / 4; i++) {
            float4 v = xr[i];
            s += v.x * v.x + v.y * v.y + v.z * v.z + v.w * v.w;
        }
        xsq_s[t] = s;
    }
    __syncthreads();

    const int arow0 = wm * 32 + (lane & 15);
    const uint32_t akb = (uint32_t)(lane >> 4) * 16;
    const int brow0 = wn * 32 + (lane & 7) + ((lane >> 4) << 3);
    const uint32_t bkb = (uint32_t)((lane >> 3) & 1) * 16;
    const int r  = lane >> 2;

    float xq[4];
#pragma unroll
    for (int mi = 0; mi < 2; mi++)
#pragma unroll
        for (int h = 0; h < 2; h++)
            xq[mi * 2 + h] = xsq_s[wm * 32 + mi * 16 + h * 8 + r];

    // ---- HOIST A: load all X fragments ONCE (tile-invariant) ----
    uint32_t ahi[8][2][4];
#pragma unroll
    for (int ks = 0; ks < 8; ks++)
#pragma unroll
        for (int mi = 0; mi < 2; mi++) {
            int row = arow0 + mi * 16;
            uint32_t off = (uint32_t)row * 256 +
                           (((uint32_t)ks * 32 + akb) ^ (uint32_t)((row & 7) << 4));
            LDSM_X4(ahi[ks][mi][0], ahi[ks][mi][1], ahi[ks][mi][2], ahi[ks][mi][3],
                    base + SM_XHI + off);
        }

    // per-slot top-3, u32 keys: (dist_bits & ~63) | local6
    uint32_t k1[4], k2[4], k3[4];
#pragma unroll
    for (int j = 0; j < 4; j++) { k1[j] = ~0u; k2[j] = ~0u; k3[j] = ~0u; }

    for (int ct = 0; ct < NTILES; ct++) {
        if (ct < NTILES - 1) { CP_WAIT(1); } else { CP_WAIT(0); }
        __syncthreads();

        const uint32_t chb = base + SM_C + (ct & 1) * 65536;
        const uint32_t clb = chb + 32768;

        float acc[2][4][4];
#pragma unroll
        for (int mi = 0; mi < 2; mi++)
#pragma unroll
            for (int ni = 0; ni < 4; ni++)
#pragma unroll
                for (int q = 0; q < 4; q++) acc[mi][ni][q] = 0.f;

#pragma unroll
        for (int ks = 0; ks < 8; ks++) {
            uint32_t bhi[4][2], blo[4][2];
#pragma unroll
            for (int nh = 0; nh < 2; nh++) {
                int row = brow0 + nh * 16;
                uint32_t off = (uint32_t)row * 256 +
                               (((uint32_t)ks * 32 + bkb) ^ (uint32_t)((row & 7) << 4));
                LDSM_X4(bhi[2 * nh][0], bhi[2 * nh][1], bhi[2 * nh + 1][0], bhi[2 * nh + 1][1],
                        chb + off);
                LDSM_X4(blo[2 * nh][0], blo[2 * nh][1], blo[2 * nh + 1][0], blo[2 * nh + 1][1],
                        clb + off);
            }
#pragma unroll
            for (int mi = 0; mi < 2; mi++)
#pragma unroll
                for (int ni = 0; ni < 4; ni++) {
                    MMA_BF16(acc[mi][ni], ahi[ks][mi], bhi[ni]);
                    MMA_BF16(acc[mi][ni], ahi[ks][mi], blo[ni]);
                }
        }

        // ---- tile epilogue: dis = xsq + csq - 2*cross, branchless top-3 (u32) ----
#pragma unroll
        for (int mi = 0; mi < 2; mi++)
#pragma unroll
            for (int ni = 0; ni < 4; ni++) {
                int cb = ct * TN + wn * 32 + ni * 8 + (lane & 3) * 2;
                float2 cq = *(const float2*)(csq_s + cb);
#pragma unroll
                for (int q = 0; q < 4; q++) {
                    int j = mi * 2 + (q >> 1);
                    int q1 = q & 1;
                    float dis = fmaf(acc[mi][ni][q], -2.f, q1 ? cq.y : cq.x) + xq[j];
                    uint32_t local6 = (uint32_t)((ct << 3) | (ni << 1) | q1);
                    uint32_t key = (__float_as_uint(dis) & ~63u) | local6;
                    uint32_t m1 = min(k1[j], key), M1 = max(k1[j], key);
                    k1[j] = m1;
                    uint32_t m2 = min(k2[j], M1),  M2 = max(k2[j], M1);
                    k2[j] = m2;
                    k3[j] = min(k3[j], M2);
                }
            }

        __syncthreads();
        if (ct + 2 < NTILES) cp_tile(ct + 2, ct & 1);
    }

    // ---- cross-thread candidate dump (reuse C buffer smem) ----
    uint32_t* rd = (uint32_t*)(sm + SM_C);   // [128 pts][16 slots][3 keys]
    int slot = wn * 4 + (lane & 3);
#pragma unroll
    for (int mi = 0; mi < 2; mi++)
#pragma unroll
        for (int h = 0; h < 2; h++) {
            int j = mi * 2 + h;
            int row = wm * 32 + mi * 16 + h * 8 + r;
            rd[row * 48 + slot * 3 + 0] = k1[j];
            rd[row * 48 + slot * 3 + 1] = k2[j];
            rd[row * 48 + slot * 3 + 2] = k3[j];
        }
    __syncthreads();

    if (t < TM) {
        // global top-4 (branchless insert, keys + decoded cluster ids)
        uint32_t tk[4] = {~0u, ~0u, ~0u, ~0u};
        int      ti[4] = {0, 0, 0, 0};
#pragma unroll
        for (int s = 0; s < 16; s++) {
#pragma unroll
            for (int e = 0; e < 3; e++) {
                uint32_t key = rd[t * 48 + s * 3 + e];
                uint32_t local = key & 63u;
                int cid = (int)(((local >> 3) << 7) | ((uint32_t)(s >> 2) << 5) |
                                (((local >> 1) & 3u) << 3) | ((uint32_t)(s & 3) << 1) |
                                (local & 1u));
#pragma unroll
                for (int u = 0; u < 4; u++) {
                    bool p = key < tk[u];
                    uint32_t km = p ? key : tk[u];  uint32_t kM = p ? tk[u] : key;
                    int im = p ? cid : ti[u];       int iM = p ? ti[u] : cid;
                    tk[u] = km; ti[u] = im; key = kM; cid = iM;
                }
            }
        }

        // ---- exact fp32 recheck of the 4 candidates ----
        const float4* xr = (const float4*)(X + (size_t)(pbase + t) * DIMS);
        float bestd = 3.4e38f;
        int   bestc = KCL;
#pragma unroll
        for (int u = 0; u < 4; u++) {
            int c = ti[u];
            const float4* pr = (const float4*)(Cf + (size_t)c * DIMS);
            float a1 = 0.f, a2 = 0.f, a3 = 0.f, a4 = 0.f;
#pragma unroll 8
            for (int i = 0; i < DIMS / 4; i++) {
                float4 xv = xr[i], cv = pr[i];
                a1 += xv.x * cv.x; a2 += xv.y * cv.y;
                a3 += xv.z * cv.z; a4 += xv.w * cv.w;
            }
            float cr = (a1 + a2) + (a3 + a4);
            float d  = fmaf(cr, -2.f, csq_s[c]);
            if (d < bestd || (d == bestd && c < bestc)) { bestd = d; bestc = c; }
        }
        out[pbase + t] = (float)bestc;   // __output__ is float32
    }
}

extern "C" void kernel_launch(void* const* d_in, const int* in_sizes, int n_in,
                              void* d_out, int out_size) {
    const float* X = (const float*)d_in[0];
    const float* C = (const float*)d_in[1];
    if (n_in >= 2 && in_sizes[0] < in_sizes[1]) {
        X = (const float*)d_in[1];
        C = (const float*)d_in[0];
    }
    float* out = (float*)d_out;

    cudaFuncSetAttribute(kmeans_mma_kernel,
                         cudaFuncAttributeMaxDynamicSharedMemorySize, SM_BYTES);

    prep_kernel<<<KCL * DIMS / 256, 256>>>(C);
    kmeans_mma_kernel<<<NPTS / TM, NTHR, SM_BYTES>>>(X, C, out);
}

// round 12
// speedup vs baseline: 1.6457x; 1.4751x over previous
#include <cuda_runtime.h>
#include <cuda_bf16.h>
#include <cstdint>

#define NPTS 262144
#define DIMS 128
#define KCL  1024
#define TM   128
#define TN   128
#define NTILES (KCL / TN)   // 8
#define NTHR 256

// ---- smem map (dynamic, from 1KB-aligned base) ----
#define SM_XHI 0
#define SM_C   32768                 // 2 buffers x 32K (hi only)
#define SM_CSQ (32768 + 65536)       // 4KB
#define SM_XSQ (SM_CSQ + 4096)       // 512B
#define SM_BYTES (SM_XSQ + 512 + 1024)

__device__ float g_csq[KCL];
__device__ __align__(16) unsigned char g_chi[KCL * DIMS * 2];  // bf16, row-major

// ---------------- PTX helpers (sm_80+ baseline ISA only) ----------------
__device__ __forceinline__ uint32_t smem_u32(const void* p) {
    uint32_t a;
    asm("{ .reg .u64 t; cvta.to.shared.u64 t, %1; cvt.u32.u64 %0, t; }" : "=r"(a) : "l"(p));
    return a;
}
#define LDSM_X4(r0, r1, r2, r3, addr) \
    asm volatile("ldmatrix.sync.aligned.m8n8.x4.shared.b16 {%0,%1,%2,%3}, [%4];" \
                 : "=r"(r0), "=r"(r1), "=r"(r2), "=r"(r3) : "r"(addr))
#define MMA_BF16(d, a, b) \
    asm volatile("mma.sync.aligned.m16n8k16.row.col.f32.bf16.bf16.f32 " \
                 "{%0,%1,%2,%3}, {%4,%5,%6,%7}, {%8,%9}, {%0,%1,%2,%3};" \
                 : "+f"((d)[0]), "+f"((d)[1]), "+f"((d)[2]), "+f"((d)[3]) \
                 : "r"((a)[0]), "r"((a)[1]), "r"((a)[2]), "r"((a)[3]), \
                   "r"((b)[0]), "r"((b)[1]))
#define CP_ASYNC16(dst, src) \
    asm volatile("cp.async.cg.shared.global [%0], [%1], 16;" :: "r"(dst), "l"(src))
#define CP_COMMIT() asm volatile("cp.async.commit_group;" ::: "memory")
#define CP_WAIT(n)  asm volatile("cp.async.wait_group %0;" :: "n"(n) : "memory")

// ---------------- prep kernel (csq + bf16 hi of C) ----------------
__global__ void prep_kernel(const float* __restrict__ C) {
    int idx = blockIdx.x * blockDim.x + threadIdx.x;   // over K*D
    if (idx < KCL * DIMS) {
        *(__nv_bfloat16*)(g_chi + (size_t)idx * 2) = __float2bfloat16(C[idx]);
    }
    if (idx < KCL) {
        const float4* row = (const float4*)(C + (size_t)idx * DIMS);
        float s = 0.f;
#pragma unroll
        for (int i = 0; i < DIMS / 4; i++) {
            float4 v = row[i];
            s += v.x * v.x + v.y * v.y + v.z * v.z + v.w * v.w;
        }
        g_csq[idx] = s;
    }
}

// ---------------- main fused kernel ----------------
__global__ void __launch_bounds__(NTHR, 2)
kmeans_mma_kernel(const float* __restrict__ X, const float* __restrict__ Cf,
                  float* __restrict__ out)
{
    extern __shared__ unsigned char smraw[];
    uint32_t base = (smem_u32(smraw) + 1023u) & ~1023u;
    unsigned char* sm = smraw + (base - smem_u32(smraw));

    const int t    = threadIdx.x;
    const int lane = t & 31;
    const int wid  = t >> 5;
    const int wm   = wid & 1;    // warp row  (64 pts)
    const int wn   = wid >> 1;   // warp col  (32 clusters)
    const int pbase = blockIdx.x * TM;

    auto cp_tile = [&](int ct, int buf) {
        uint32_t dbase = base + SM_C + buf * 32768;
#pragma unroll
        for (int i = 0; i < 8; i++) {
            int idx = t + NTHR * i;          // 2048 uint4
            int row = idx >> 4;
            int c   = idx & 15;
            uint32_t doff = (uint32_t)row * 256 + (uint32_t)((c ^ (row & 7)) << 4);
            size_t   soff = (size_t)ct * 32768 + (size_t)row * 256 + (size_t)c * 16;
            CP_ASYNC16(dbase + doff, g_chi + soff);
        }
        CP_COMMIT();
    };
    cp_tile(0, 0);
    cp_tile(1, 1);

    float* csq_s = (float*)(sm + SM_CSQ);
    float* xsq_s = (float*)(sm + SM_XSQ);
#pragma unroll
    for (int k = 0; k < 4; k++) csq_s[t + NTHR * k] = g_csq[t + NTHR * k];

    // ---- build X hi tile in smem (swizzled 256B rows) ----
    {
        const float4* Xg = (const float4*)(X + (size_t)pbase * DIMS);
#pragma unroll
        for (int i = 0; i < 8; i++) {
            int idx = t + NTHR * i;          // 2048 chunks (8 dims each)
            int row = idx >> 4;
            int c   = idx & 15;
            float4 v0 = Xg[row * 32 + c * 2];
            float4 v1 = Xg[row * 32 + c * 2 + 1];
            float f[8] = {v0.x, v0.y, v0.z, v0.w, v1.x, v1.y, v1.z, v1.w};
            union { __nv_bfloat16 b[8]; uint4 u; } ph;
#pragma unroll
            for (int e = 0; e < 8; e++) ph.b[e] = __float2bfloat16(f[e]);
            uint32_t doff = (uint32_t)row * 256 + (uint32_t)((c ^ (row & 7)) << 4);
            *(uint4*)(sm + SM_XHI + doff) = ph.u;
        }
    }

    // ---- per-point ||x||^2 (scores positive -> raw-bits-sortable) ----
    if (t < TM) {
        const float4* xr = (const float4*)(X + (size_t)(pbase + t) * DIMS);
        float s = 0.f;
#pragma unroll 8
        for (int i = 0; i < DIMS / 4; i++) {
            float4 v = xr[i];
            s += v.x * v.x + v.y * v.y + v.z * v.z + v.w * v.w;
        }
        xsq_s[t] = s;
    }
    __syncthreads();

    const int arow0 = wm * 64 + (lane & 15);
    const uint32_t akb = (uint32_t)(lane >> 4) * 16;
    const int brow0 = wn * 32 + (lane & 7) + ((lane >> 4) << 3);
    const uint32_t bkb = (uint32_t)((lane >> 3) & 1) * 16;
    const int r  = lane >> 2;

    float xq[8];
#pragma unroll
    for (int mi = 0; mi < 4; mi++)
#pragma unroll
        for (int h = 0; h < 2; h++)
            xq[mi * 2 + h] = xsq_s[wm * 64 + mi * 16 + h * 8 + r];

    // per-slot top-2, u32 keys: (dist_bits & ~63) | local6   (64 clusters/slot)
    uint32_t k1[8], k2[8];
#pragma unroll
    for (int j = 0; j < 8; j++) { k1[j] = ~0u; k2[j] = ~0u; }

    for (int ct = 0; ct < NTILES; ct++) {
        if (ct < NTILES - 1) { CP_WAIT(1); } else { CP_WAIT(0); }
        __syncthreads();

        const uint32_t chb = base + SM_C + (ct & 1) * 32768;

        float acc[4][4][4];
#pragma unroll
        for (int mi = 0; mi < 4; mi++)
#pragma unroll
            for (int ni = 0; ni < 4; ni++)
#pragma unroll
                for (int q = 0; q < 4; q++) acc[mi][ni][q] = 0.f;

#pragma unroll
        for (int ks = 0; ks < 8; ks++) {
            uint32_t ahi[4][4], bhi[4][2];
#pragma unroll
            for (int mi = 0; mi < 4; mi++) {
                int row = arow0 + mi * 16;
                uint32_t off = (uint32_t)row * 256 +
                               (((uint32_t)ks * 32 + akb) ^ (uint32_t)((row & 7) << 4));
                LDSM_X4(ahi[mi][0], ahi[mi][1], ahi[mi][2], ahi[mi][3], base + SM_XHI + off);
            }
#pragma unroll
            for (int nh = 0; nh < 2; nh++) {
                int row = brow0 + nh * 16;
                uint32_t off = (uint32_t)row * 256 +
                               (((uint32_t)ks * 32 + bkb) ^ (uint32_t)((row & 7) << 4));
                LDSM_X4(bhi[2 * nh][0], bhi[2 * nh][1], bhi[2 * nh + 1][0], bhi[2 * nh + 1][1],
                        chb + off);
            }
#pragma unroll
            for (int mi = 0; mi < 4; mi++)
#pragma unroll
                for (int ni = 0; ni < 4; ni++)
                    MMA_BF16(acc[mi][ni], ahi[mi], bhi[ni]);
        }

        // ---- tile epilogue: dis = xsq + csq - 2*cross, branchless top-2 ----
#pragma unroll
        for (int mi = 0; mi < 4; mi++)
#pragma unroll
            for (int ni = 0; ni < 4; ni++) {
                int cb = ct * TN + wn * 32 + ni * 8 + (lane & 3) * 2;
                float2 cq = *(const float2*)(csq_s + cb);
#pragma unroll
                for (int q = 0; q < 4; q++) {
                    int j = mi * 2 + (q >> 1);
                    int q1 = q & 1;
                    float dis = fmaf(acc[mi][ni][q], -2.f, q1 ? cq.y : cq.x) + xq[j];
                    uint32_t local6 = (uint32_t)((ct << 3) | (ni << 1) | q1);
                    uint32_t key = (__float_as_uint(dis) & ~63u) | local6;
                    uint32_t m1 = min(k1[j], key), M1 = max(k1[j], key);
                    k1[j] = m1;
                    k2[j] = min(k2[j], M1);
                }
            }

        __syncthreads();
        if (ct + 2 < NTILES) cp_tile(ct + 2, ct & 1);
    }

    // ---- cross-thread candidate dump (reuse C buffer smem) ----
    uint32_t* rd = (uint32_t*)(sm + SM_C);   // [128 pts][16 slots][2 keys] = 16KB
    int slot = wn * 4 + (lane & 3);
#pragma unroll
    for (int mi = 0; mi < 4; mi++)
#pragma unroll
        for (int h = 0; h < 2; h++) {
            int j = mi * 2 + h;
            int row = wm * 64 + mi * 16 + h * 8 + r;
            rd[row * 32 + slot * 2 + 0] = k1[j];
            rd[row * 32 + slot * 2 + 1] = k2[j];
        }
    __syncthreads();

    if (t < TM) {
        // global top-4 (branchless insert, keys + decoded cluster ids)
        uint32_t tk[4] = {~0u, ~0u, ~0u, ~0u};
        int      ti[4] = {0, 0, 0, 0};
#pragma unroll
        for (int s = 0; s < 16; s++) {
#pragma unroll
            for (int e = 0; e < 2; e++) {
                uint32_t key = rd[t * 32 + s * 2 + e];
                uint32_t local = key & 63u;
                int cid = (int)(((local >> 3) << 7) | ((uint32_t)(s >> 2) << 5) |
                                (((local >> 1) & 3u) << 3) | ((uint32_t)(s & 3) << 1) |
                                (local & 1u));
#pragma unroll
                for (int u = 0; u < 4; u++) {
                    bool p = key < tk[u];
                    uint32_t km = p ? key : tk[u];  uint32_t kM = p ? tk[u] : key;
                    int im = p ? cid : ti[u];       int iM = p ? ti[u] : cid;
                    tk[u] = km; ti[u] = im; key = kM; cid = iM;
                }
            }
        }

        // ---- exact fp32 recheck of the 4 candidates ----
        const float4* xr = (const float4*)(X + (size_t)(pbase + t) * DIMS);
        float bestd = 3.4e38f;
        int   bestc = KCL;
#pragma unroll
        for (int u = 0; u < 4; u++) {
            int c = ti[u];
            const float4* pr = (const float4*)(Cf + (size_t)c * DIMS);
            float a1 = 0.f, a2 = 0.f, a3 = 0.f, a4 = 0.f;
#pragma unroll 8
            for (int i = 0; i < DIMS / 4; i++) {
                float4 xv = xr[i], cv = pr[i];
                a1 += xv.x * cv.x; a2 += xv.y * cv.y;
                a3 += xv.z * cv.z; a4 += xv.w * cv.w;
            }
            float cr = (a1 + a2) + (a3 + a4);
            float d  = fmaf(cr, -2.f, csq_s[c]);
            if (d < bestd || (d == bestd && c < bestc)) { bestd = d; bestc = c; }
        }
        out[pbase + t] = (float)bestc;   // __output__ is float32
    }
}

extern "C" void kernel_launch(void* const* d_in, const int* in_sizes, int n_in,
                              void* d_out, int out_size) {
    const float* X = (const float*)d_in[0];
    const float* C = (const float*)d_in[1];
    if (n_in >= 2 && in_sizes[0] < in_sizes[1]) {
        X = (const float*)d_in[1];
        C = (const float*)d_in[0];
    }
    float* out = (float*)d_out;

    cudaFuncSetAttribute(kmeans_mma_kernel,
                         cudaFuncAttributeMaxDynamicSharedMemorySize, SM_BYTES);

    prep_kernel<<<KCL * DIMS / 256, 256>>>(C);
    kmeans_mma_kernel<<<NPTS / TM, NTHR, SM_BYTES>>>(X, C, out);
}

// round 13
// speedup vs baseline: 2.4395x; 1.4824x over previous
#include <cuda_runtime.h>
#include <cuda_bf16.h>
#include <cstdint>

#define NPTS 262144
#define DIMS 128
#define KCL  1024
#define TM   128
#define TN   128
#define NTILES (KCL / TN)   // 8
#define NTHR 256

// ---- smem map (dynamic, from 1KB-aligned base) ----
#define SM_XHI 0
#define SM_C   32768                 // 2 buffers x 32K (hi only)
#define SM_CSQ (32768 + 65536)       // 4KB
#define SM_XSQ (SM_CSQ + 4096)       // 512B
#define SM_BYTES (SM_XSQ + 512 + 1024)

__device__ float g_csq[KCL];
__device__ __align__(16) unsigned char g_chi[KCL * DIMS * 2];  // bf16, row-major

// ---------------- PTX helpers (sm_80+ baseline ISA only) ----------------
__device__ __forceinline__ uint32_t smem_u32(const void* p) {
    uint32_t a;
    asm("{ .reg .u64 t; cvta.to.shared.u64 t, %1; cvt.u32.u64 %0, t; }" : "=r"(a) : "l"(p));
    return a;
}
#define LDSM_X4(r0, r1, r2, r3, addr) \
    asm volatile("ldmatrix.sync.aligned.m8n8.x4.shared.b16 {%0,%1,%2,%3}, [%4];" \
                 : "=r"(r0), "=r"(r1), "=r"(r2), "=r"(r3) : "r"(addr))
#define MMA_BF16(d, a, b) \
    asm volatile("mma.sync.aligned.m16n8k16.row.col.f32.bf16.bf16.f32 " \
                 "{%0,%1,%2,%3}, {%4,%5,%6,%7}, {%8,%9}, {%0,%1,%2,%3};" \
                 : "+f"((d)[0]), "+f"((d)[1]), "+f"((d)[2]), "+f"((d)[3]) \
                 : "r"((a)[0]), "r"((a)[1]), "r"((a)[2]), "r"((a)[3]), \
                   "r"((b)[0]), "r"((b)[1]))
#define CP_ASYNC16(dst, src) \
    asm volatile("cp.async.cg.shared.global [%0], [%1], 16;" :: "r"(dst), "l"(src))
#define CP_COMMIT() asm volatile("cp.async.commit_group;" ::: "memory")
#define CP_WAIT(n)  asm volatile("cp.async.wait_group %0;" :: "n"(n) : "memory")

// ---------------- prep kernel (csq + bf16 hi of C) ----------------
__global__ void prep_kernel(const float* __restrict__ C) {
    int idx = blockIdx.x * blockDim.x + threadIdx.x;   // over K*D
    if (idx < KCL * DIMS) {
        *(__nv_bfloat16*)(g_chi + (size_t)idx * 2) = __float2bfloat16(C[idx]);
    }
    if (idx < KCL) {
        const float4* row = (const float4*)(C + (size_t)idx * DIMS);
        float s = 0.f;
#pragma unroll
        for (int i = 0; i < DIMS / 4; i++) {
            float4 v = row[i];
            s += v.x * v.x + v.y * v.y + v.z * v.z + v.w * v.w;
        }
        g_csq[idx] = s;
    }
}

// ---------------- main fused kernel ----------------
__global__ void __launch_bounds__(NTHR, 2)
kmeans_mma_kernel(const float* __restrict__ X, const float* __restrict__ Cf,
                  float* __restrict__ out)
{
    extern __shared__ unsigned char smraw[];
    uint32_t base = (smem_u32(smraw) + 1023u) & ~1023u;
    unsigned char* sm = smraw + (base - smem_u32(smraw));

    const int t    = threadIdx.x;
    const int lane = t & 31;
    const int wid  = t >> 5;
    const int wm   = wid & 1;    // warp row  (64 pts)
    const int wn   = wid >> 1;   // warp col  (32 clusters)
    const int pbase = blockIdx.x * TM;

    auto cp_tile = [&](int ct, int buf) {
        uint32_t dbase = base + SM_C + buf * 32768;
#pragma unroll
        for (int i = 0; i < 8; i++) {
            int idx = t + NTHR * i;          // 2048 uint4
            int row = idx >> 4;
            int c   = idx & 15;
            uint32_t doff = (uint32_t)row * 256 + (uint32_t)((c ^ (row & 7)) << 4);
            size_t   soff = (size_t)ct * 32768 + (size_t)row * 256 + (size_t)c * 16;
            CP_ASYNC16(dbase + doff, g_chi + soff);
        }
        CP_COMMIT();
    };
    cp_tile(0, 0);
    cp_tile(1, 1);

    float* csq_s = (float*)(sm + SM_CSQ);
    float* xsq_s = (float*)(sm + SM_XSQ);
#pragma unroll
    for (int k = 0; k < 4; k++) csq_s[t + NTHR * k] = g_csq[t + NTHR * k];

    // ---- build X hi tile in smem (swizzled 256B rows) + fused ||x||^2 ----
    {
        const float4* Xg = (const float4*)(X + (size_t)pbase * DIMS);
#pragma unroll
        for (int i = 0; i < 8; i++) {
            int idx = t + NTHR * i;          // 2048 chunks (8 dims each)
            int row = idx >> 4;
            int c   = idx & 15;
            float4 v0 = Xg[row * 32 + c * 2];
            float4 v1 = Xg[row * 32 + c * 2 + 1];
            float f[8] = {v0.x, v0.y, v0.z, v0.w, v1.x, v1.y, v1.z, v1.w};
            union { __nv_bfloat16 b[8]; uint4 u; } ph;
            float ss = 0.f;
#pragma unroll
            for (int e = 0; e < 8; e++) {
                ph.b[e] = __float2bfloat16(f[e]);
                ss = fmaf(f[e], f[e], ss);
            }
            uint32_t doff = (uint32_t)row * 256 + (uint32_t)((c ^ (row & 7)) << 4);
            *(uint4*)(sm + SM_XHI + doff) = ph.u;
            // 16 lanes share a row -> reduce within the 16-lane group
#pragma unroll
            for (int off = 8; off; off >>= 1)
                ss += __shfl_xor_sync(0xFFFFFFFFu, ss, off);
            if ((t & 15) == 0) xsq_s[row] = ss;
        }
    }
    __syncthreads();

    const int arow0 = wm * 64 + (lane & 15);
    const uint32_t akb = (uint32_t)(lane >> 4) * 16;
    const int brow0 = wn * 32 + (lane & 7) + ((lane >> 4) << 3);
    const uint32_t bkb = (uint32_t)((lane >> 3) & 1) * 16;
    const int r  = lane >> 2;

    float xq[8];
#pragma unroll
    for (int mi = 0; mi < 4; mi++)
#pragma unroll
        for (int h = 0; h < 2; h++)
            xq[mi * 2 + h] = xsq_s[wm * 64 + mi * 16 + h * 8 + r];

    // per-slot top-2, u32 keys: (dist_bits & ~63) | local6   (64 clusters/slot)
    uint32_t k1[8], k2[8];
#pragma unroll
    for (int j = 0; j < 8; j++) { k1[j] = ~0u; k2[j] = ~0u; }

    for (int ct = 0; ct < NTILES; ct++) {
        if (ct < NTILES - 1) { CP_WAIT(1); } else { CP_WAIT(0); }
        __syncthreads();

        const uint32_t chb = base + SM_C + (ct & 1) * 32768;

        float acc[4][4][4];
#pragma unroll
        for (int mi = 0; mi < 4; mi++)
#pragma unroll
            for (int ni = 0; ni < 4; ni++)
#pragma unroll
                for (int q = 0; q < 4; q++) acc[mi][ni][q] = 0.f;

#pragma unroll
        for (int ks = 0; ks < 8; ks++) {
            uint32_t ahi[4][4], bhi[4][2];
#pragma unroll
            for (int mi = 0; mi < 4; mi++) {
                int row = arow0 + mi * 16;
                uint32_t off = (uint32_t)row * 256 +
                               (((uint32_t)ks * 32 + akb) ^ (uint32_t)((row & 7) << 4));
                LDSM_X4(ahi[mi][0], ahi[mi][1], ahi[mi][2], ahi[mi][3], base + SM_XHI + off);
            }
#pragma unroll
            for (int nh = 0; nh < 2; nh++) {
                int row = brow0 + nh * 16;
                uint32_t off = (uint32_t)row * 256 +
                               (((uint32_t)ks * 32 + bkb) ^ (uint32_t)((row & 7) << 4));
                LDSM_X4(bhi[2 * nh][0], bhi[2 * nh][1], bhi[2 * nh + 1][0], bhi[2 * nh + 1][1],
                        chb + off);
            }
#pragma unroll
            for (int mi = 0; mi < 4; mi++)
#pragma unroll
                for (int ni = 0; ni < 4; ni++)
                    MMA_BF16(acc[mi][ni], ahi[mi], bhi[ni]);
        }

        // ---- tile epilogue: dis = xsq + csq - 2*cross, branchless top-2 ----
#pragma unroll
        for (int mi = 0; mi < 4; mi++)
#pragma unroll
            for (int ni = 0; ni < 4; ni++) {
                int cb = ct * TN + wn * 32 + ni * 8 + (lane & 3) * 2;
                float2 cq = *(const float2*)(csq_s + cb);
#pragma unroll
                for (int q = 0; q < 4; q++) {
                    int j = mi * 2 + (q >> 1);
                    int q1 = q & 1;
                    float dis = fmaf(acc[mi][ni][q], -2.f, q1 ? cq.y : cq.x) + xq[j];
                    uint32_t local6 = (uint32_t)((ct << 3) | (ni << 1) | q1);
                    uint32_t key = (__float_as_uint(dis) & ~63u) | local6;
                    uint32_t m1 = min(k1[j], key), M1 = max(k1[j], key);
                    k1[j] = m1;
                    k2[j] = min(k2[j], M1);
                }
            }

        __syncthreads();
        if (ct + 2 < NTILES) cp_tile(ct + 2, ct & 1);
    }

    // ---- cross-thread candidate dump (reuse C buffer smem) ----
    uint32_t* rd = (uint32_t*)(sm + SM_C);             // [128 pts][32 keys] = 16KB
    int4*     cand_s = (int4*)(sm + SM_C + 16384);     // [128 pts] top-4 ids
    int slot = wn * 4 + (lane & 3);
#pragma unroll
    for (int mi = 0; mi < 4; mi++)
#pragma unroll
        for (int h = 0; h < 2; h++) {
            int j = mi * 2 + h;
            int row = wm * 64 + mi * 16 + h * 8 + r;
            rd[row * 32 + slot * 2 + 0] = k1[j];
            rd[row * 32 + slot * 2 + 1] = k2[j];
        }
    __syncthreads();

    // ---- phase A: per-point global top-4 id list (threads 0..127) ----
    if (t < TM) {
        uint32_t tk[4] = {~0u, ~0u, ~0u, ~0u};
        int      ti[4] = {0, 0, 0, 0};
#pragma unroll
        for (int s = 0; s < 16; s++) {
#pragma unroll
            for (int e = 0; e < 2; e++) {
                uint32_t key = rd[t * 32 + s * 2 + e];
                uint32_t local = key & 63u;
                int cid = (int)(((local >> 3) << 7) | ((uint32_t)(s >> 2) << 5) |
                                (((local >> 1) & 3u) << 3) | ((uint32_t)(s & 3) << 1) |
                                (local & 1u));
#pragma unroll
                for (int u = 0; u < 4; u++) {
                    bool p = key < tk[u];
                    uint32_t km = p ? key : tk[u];  uint32_t kM = p ? tk[u] : key;
                    int im = p ? cid : ti[u];       int iM = p ? ti[u] : cid;
                    tk[u] = km; ti[u] = im; key = kM; cid = iM;
                }
            }
        }
        cand_s[t] = make_int4(ti[0], ti[1], ti[2], ti[3]);
    }
    __syncthreads();

    // ---- phase B: warp-cooperative exact fp32 recheck (coalesced) ----
    // warp w handles points w*16 .. w*16+15; all 32 lanes cover one 128-float row
    {
        const int p0 = wid * 16;
        for (int pp = 0; pp < 16; pp++) {
            int p = p0 + pp;
            int4 cd = cand_s[p];
            float4 xv = ((const float4*)(X + (size_t)(pbase + p) * DIMS))[lane];
            int cids[4] = {cd.x, cd.y, cd.z, cd.w};
            float dot[4];
#pragma unroll
            for (int u = 0; u < 4; u++) {
                float4 cv = ((const float4*)(Cf + (size_t)cids[u] * DIMS))[lane];
                float s = xv.x * cv.x + xv.y * cv.y + xv.z * cv.z + xv.w * cv.w;
#pragma unroll
                for (int off = 16; off; off >>= 1)
                    s += __shfl_xor_sync(0xFFFFFFFFu, s, off);
                dot[u] = s;
            }
            if (lane == 0) {
                float bestd = 3.4e38f;
                int   bestc = KCL;
#pragma unroll
                for (int u = 0; u < 4; u++) {
                    float d = fmaf(dot[u], -2.f, csq_s[cids[u]]);
                    if (d < bestd || (d == bestd && cids[u] < bestc)) {
                        bestd = d; bestc = cids[u];
                    }
                }
                out[pbase + p] = (float)bestc;   // __output__ is float32
            }
        }
    }
}

extern "C" void kernel_launch(void* const* d_in, const int* in_sizes, int n_in,
                              void* d_out, int out_size) {
    const float* X = (const float*)d_in[0];
    const float* C = (const float*)d_in[1];
    if (n_in >= 2 && in_sizes[0] < in_sizes[1]) {
        X = (const float*)d_in[1];
        C = (const float*)d_in[0];
    }
    float* out = (float*)d_out;

    cudaFuncSetAttribute(kmeans_mma_kernel,
                         cudaFuncAttributeMaxDynamicSharedMemorySize, SM_BYTES);

    prep_kernel<<<KCL * DIMS / 256, 256>>>(C);
    kmeans_mma_kernel<<<NPTS / TM, NTHR, SM_BYTES>>>(X, C, out);
}